// round 15
// baseline (speedup 1.0000x reference)
#include <cuda_runtime.h>
#include <math.h>

#define H 512
#define W 512
#define NS 14            // number of gaussian scales (K+1)
#define NK 13            // number of DoG planes (K)
#define MAXR 43
#define NROWS (NK*H)
#define THRESH 0.001f
#define MAXPEAKS 32768
#define HW (H*W)

// ---- scratch (static device memory; no allocations allowed) ----
__device__ float  d_tmpf[NS*H*W];     // after horizontal blur (fp32-rounded)
// g pyramid with 1024-float guard pads on both sides so peak_k can read
// halo cells unclamped (garbage there only consumed as neighbors of
// border-excluded pixels -> never affects results).
__device__ __align__(16) float d_gbuf[NS*H*W + 2048];
#define D_G (d_gbuf + 1024)
__device__ float  d_kx[NS*96];        // 1D kernels, fp32-rounded coeffs (padded)
__device__ int    d_rad[NS];
__device__ float  d_sig[NS];
__device__ unsigned d_maskw[NROWS*16];// 512-bit peak mask per (k,y) row
                                      // (k=0 and k=12 rows: never written, BSS zero)
__device__ int    d_pcnt[NROWS*4];    // per-(row, x-block) popcounts (k=0/12: BSS zero)
__device__ int    d_rowcnt[NROWS];    // exclusive offsets after scan
__device__ int    d_total;            // total peak count

// Anchored Fast2Sum: hi >= 2 > b >= 0 always -> error extraction exact.
#define F2S(hi_, lo_, b_) do { \
    float t2_ = __fadd_rn(hi_, b_); \
    float u_  = __fsub_rn(t2_, hi_); \
    float e_  = __fsub_rn(b_, u_); \
    hi_ = t2_; \
    lo_ = __fadd_rn(lo_, e_); \
} while (0)

// ---------------------------------------------------------------
// Build normalized 1D gaussian kernels in fp64, round to fp32.
// ---------------------------------------------------------------
__global__ void build_kernels_k(const float* __restrict__ sigma_list) {
    int i   = blockIdx.x;
    int tid = threadIdx.x;      // 128 threads
    float sf = sigma_list[i];
    double s = (double)sf;
    int r   = (int)floor(4.0 * s + 0.5);   // TRUNCATE=4
    int n   = 2 * r + 1;
    __shared__ double tmp[96];
    __shared__ double ssum;
    if (tid < n) {
        double mean = 0.5 * (double)(n - 1);
        double d = ((double)tid - mean) / (2.0 * s);
        tmp[tid] = exp(-(d * d));
    }
    __syncthreads();
    if (tid == 0) {
        double acc = 0.0;
        for (int j = 0; j < n; j++) acc += tmp[j];
        ssum = acc;
        d_rad[i] = r;
        d_sig[i] = sf;
    }
    __syncthreads();
    if (tid < 96) d_kx[i*96 + tid] = (tid < n) ? (float)(tmp[tid] / ssum) : 0.f;
}

// ---------------------------------------------------------------
// Horizontal pass. Symmetric pairing (a_l+a_r)*k, FOUR pairs folded
// per anchored Fast2Sum (K=4 block compensation): 1.5 fma-ops/tap.
// 8-wide sliding windows, step 4. Remainder pairs (<=3) + center
// read smem directly. 4 outputs/thread. blockDim 128, grid (H, NS).
// ---------------------------------------------------------------
__global__ void hblur_k(const float* __restrict__ x) {
    int y  = blockIdx.x;
    int sc = blockIdx.y;
    int r  = d_rad[sc];
    int n  = 2 * r + 1;
    __shared__ float srow[W + 2*MAXR + 8];
    __shared__ float sk[96];
    int tid = threadIdx.x;
    for (int i = tid; i < W + 2*r + 4; i += 128) {
        int xx = i - r;
        srow[i] = (xx >= 0 && xx < W) ? x[y*W + xx] : 0.f;
    }
    for (int i = tid; i < n; i += 128) sk[i] = d_kx[sc*96 + i];
    __syncthreads();

    int xo = tid * 4;
    float wl[8], wr[8];
    #pragma unroll
    for (int q = 0; q < 8; q++) {
        wl[q] = srow[xo + q];            // wl[q] = srow[xo + j + q]
        wr[q] = srow[xo + n - 4 + q];    // wr[q] = srow[xo + n-4-j + q]
    }
    float hi[4] = {2.f, 2.f, 2.f, 2.f};
    float lo[4] = {0.f, 0.f, 0.f, 0.f};

    int j = 0;
    #pragma unroll 2
    for (; j + 3 < r; j += 4) {
        float k0 = sk[j], k1 = sk[j+1], k2 = sk[j+2], k3 = sk[j+3];
        #pragma unroll
        for (int t = 0; t < 4; t++) {
            float b = __fmul_rn(__fadd_rn(wl[t],   wr[t+3]), k0);
            b = __fmaf_rn(__fadd_rn(wl[t+1], wr[t+2]), k1, b);
            b = __fmaf_rn(__fadd_rn(wl[t+2], wr[t+1]), k2, b);
            b = __fmaf_rn(__fadd_rn(wl[t+3], wr[t]),   k3, b);
            F2S(hi[t], lo[t], b);
        }
        wl[0]=wl[4]; wl[1]=wl[5]; wl[2]=wl[6]; wl[3]=wl[7];
        wl[4]=srow[xo+j+8];  wl[5]=srow[xo+j+9];
        wl[6]=srow[xo+j+10]; wl[7]=srow[xo+j+11];
        wr[7]=wr[3]; wr[6]=wr[2]; wr[5]=wr[1]; wr[4]=wr[0];
        wr[0]=srow[xo+n-8-j]; wr[1]=srow[xo+n-7-j];
        wr[2]=srow[xo+n-6-j]; wr[3]=srow[xo+n-5-j];
    }
    // remainder pairs (<=3), direct smem reads
    for (; j < r; j++) {
        float kj = sk[j];
        #pragma unroll
        for (int t = 0; t < 4; t++) {
            float s = __fadd_rn(srow[xo+t+j], srow[xo+t+n-1-j]);
            float b = __fmul_rn(s, kj);
            F2S(hi[t], lo[t], b);
        }
    }
    // center tap
    {
        float kc = sk[r];
        #pragma unroll
        for (int t = 0; t < 4; t++) {
            float b = __fmul_rn(srow[xo+t+r], kc);
            F2S(hi[t], lo[t], b);
        }
    }
    float4 o;
    o.x = __fadd_rn(__fsub_rn(hi[0], 2.f), lo[0]);
    o.y = __fadd_rn(__fsub_rn(hi[1], 2.f), lo[1]);
    o.z = __fadd_rn(__fsub_rn(hi[2], 2.f), lo[2]);
    o.w = __fadd_rn(__fsub_rn(hi[3], 2.f), lo[3]);
    *(float4*)(d_tmpf + (size_t)(sc*H + y) * W + xo) = o;
}

// ---------------------------------------------------------------
// Vertical pass, same K=4 block-compensated scheme on fp32 inputs.
// blockDim (32,8), grid (16,16,NS).
// ---------------------------------------------------------------
#define VTX 32
#define VTY 32
__global__ void vblur_k() {
    int sc = blockIdx.z;
    int x0 = blockIdx.x * VTX;
    int y0 = blockIdx.y * VTY;
    int r  = d_rad[sc];
    int n  = 2 * r + 1;
    __shared__ float tile[(VTY + 2*MAXR + 4) * VTX];
    __shared__ float sk[96];
    int tx  = threadIdx.x;
    int tid = tx + threadIdx.y * VTX;   // 256 threads
    int rows = VTY + 2 * r + 3;
    const float* inp = d_tmpf + (size_t)sc * HW;
    for (int i = tid; i < rows * VTX; i += 256) {
        int rr = i / VTX, cc = i % VTX;
        int gy = y0 - r + rr;
        tile[i] = (gy >= 0 && gy < H) ? inp[gy*W + x0 + cc] : 0.f;
    }
    for (int i = tid; i < n; i += 256) sk[i] = d_kx[sc*96 + i];
    __syncthreads();

    int yo = threadIdx.y * 4;
    float wl[8], wr[8];
    #pragma unroll
    for (int q = 0; q < 8; q++) {
        wl[q] = tile[(yo + q)*VTX + tx];
        wr[q] = tile[(yo + n - 4 + q)*VTX + tx];
    }
    float hi[4] = {2.f, 2.f, 2.f, 2.f};
    float lo[4] = {0.f, 0.f, 0.f, 0.f};

    int j = 0;
    #pragma unroll 2
    for (; j + 3 < r; j += 4) {
        float k0 = sk[j], k1 = sk[j+1], k2 = sk[j+2], k3 = sk[j+3];
        #pragma unroll
        for (int t = 0; t < 4; t++) {
            float b = __fmul_rn(__fadd_rn(wl[t],   wr[t+3]), k0);
            b = __fmaf_rn(__fadd_rn(wl[t+1], wr[t+2]), k1, b);
            b = __fmaf_rn(__fadd_rn(wl[t+2], wr[t+1]), k2, b);
            b = __fmaf_rn(__fadd_rn(wl[t+3], wr[t]),   k3, b);
            F2S(hi[t], lo[t], b);
        }
        wl[0]=wl[4]; wl[1]=wl[5]; wl[2]=wl[6]; wl[3]=wl[7];
        wl[4]=tile[(yo+j+8)*VTX+tx];  wl[5]=tile[(yo+j+9)*VTX+tx];
        wl[6]=tile[(yo+j+10)*VTX+tx]; wl[7]=tile[(yo+j+11)*VTX+tx];
        wr[7]=wr[3]; wr[6]=wr[2]; wr[5]=wr[1]; wr[4]=wr[0];
        wr[0]=tile[(yo+n-8-j)*VTX+tx]; wr[1]=tile[(yo+n-7-j)*VTX+tx];
        wr[2]=tile[(yo+n-6-j)*VTX+tx]; wr[3]=tile[(yo+n-5-j)*VTX+tx];
    }
    for (; j < r; j++) {
        float kj = sk[j];
        #pragma unroll
        for (int t = 0; t < 4; t++) {
            float s = __fadd_rn(tile[(yo+t+j)*VTX+tx],
                                tile[(yo+t+n-1-j)*VTX+tx]);
            float b = __fmul_rn(s, kj);
            F2S(hi[t], lo[t], b);
        }
    }
    {
        float kc = sk[r];
        #pragma unroll
        for (int t = 0; t < 4; t++) {
            float b = __fmul_rn(tile[(yo+t+r)*VTX+tx], kc);
            F2S(hi[t], lo[t], b);
        }
    }
    float* outp = D_G + (size_t)sc * HW;
    #pragma unroll
    for (int t = 0; t < 4; t++)
        outp[(y0 + yo + t)*W + x0 + tx] =
            __fadd_rn(__fsub_rn(hi[t], 2.f), lo[t]);
}

// ---------------------------------------------------------------
// FUSED DoG + peak, separable max-pool, vectorized fill.
// pk = (c > THRESH) && (c >= max27) == reference semantics exactly.
// blockDim (32,8), grid (4, 64, NK-2).
// ---------------------------------------------------------------
#define PTX 128
#define PTY 8
#define TC2 136
#define NV 34
__global__ void peak_k() {
    int k  = blockIdx.z + 1;            // 1..11
    int y0 = blockIdx.y * PTY;
    int x0 = blockIdx.x * PTX;
    __shared__ __align__(16) float szmax[PTY + 2][TC2];
    __shared__ __align__(16) float sdogc[PTY + 2][TC2];
    __shared__ float svmax[PTY][TC2];
    int tx = threadIdx.x;
    int ty = threadIdx.y;
    int tid = tx + ty * 32;             // 256 threads

    float sgm1 = d_sig[k-1], sg0 = d_sig[k], sgp1 = d_sig[k+1];
    const float* gm1 = D_G + (size_t)(k-1) * HW;
    const float* g0  = gm1 + HW;
    const float* gp1 = g0  + HW;
    const float* gp2 = gp1 + HW;

    for (int idx = tid; idx < (PTY + 2) * NV; idx += 256) {
        int rr = idx / NV, cc = idx - rr * NV;
        int gi = (y0 - 1 + rr) * W + (x0 - 4) + cc * 4;
        float4 a = *(const float4*)(gm1 + gi);
        float4 b = *(const float4*)(g0  + gi);
        float4 c = *(const float4*)(gp1 + gi);
        float4 d = *(const float4*)(gp2 + gi);
        float4 dc, zm;
        {
            float m1 = (a.x - b.x) * sgm1;
            dc.x     = (b.x - c.x) * sg0;
            float p1 = (c.x - d.x) * sgp1;
            zm.x = fmaxf(fmaxf(m1, dc.x), p1);
        }
        {
            float m1 = (a.y - b.y) * sgm1;
            dc.y     = (b.y - c.y) * sg0;
            float p1 = (c.y - d.y) * sgp1;
            zm.y = fmaxf(fmaxf(m1, dc.y), p1);
        }
        {
            float m1 = (a.z - b.z) * sgm1;
            dc.z     = (b.z - c.z) * sg0;
            float p1 = (c.z - d.z) * sgp1;
            zm.z = fmaxf(fmaxf(m1, dc.z), p1);
        }
        {
            float m1 = (a.w - b.w) * sgm1;
            dc.w     = (b.w - c.w) * sg0;
            float p1 = (c.w - d.w) * sgp1;
            zm.w = fmaxf(fmaxf(m1, dc.w), p1);
        }
        *(float4*)&szmax[rr][cc*4] = zm;
        *(float4*)&sdogc[rr][cc*4] = dc;
    }
    __syncthreads();

    #pragma unroll
    for (int cc = tx; cc < TC2; cc += 32)
        svmax[ty][cc] = fmaxf(fmaxf(szmax[ty][cc], szmax[ty+1][cc]),
                              szmax[ty+2][cc]);
    __syncthreads();

    int y = y0 + ty;
    int cnt = 0;
    #pragma unroll
    for (int q = 0; q < 4; q++) {
        int x  = x0 + q * 32 + tx;
        int lx = q * 32 + tx + 4;
        bool pk = false;
        if (y >= 1 && y <= H-2 && x >= 1 && x <= W-2) {
            float c = sdogc[ty+1][lx];
            if (c > THRESH) {
                float m = fmaxf(fmaxf(svmax[ty][lx-1], svmax[ty][lx]),
                                svmax[ty][lx+1]);
                pk = (c >= m);
            }
        }
        unsigned wmask = __ballot_sync(0xFFFFFFFFu, pk);
        if (tx == 0) {
            d_maskw[(k*H + y)*16 + (x0/32 + q)] = wmask;
            cnt += __popc(wmask);
        }
    }
    if (tx == 0) d_pcnt[(k*H + y)*4 + blockIdx.x] = cnt;
}

// ---------------------------------------------------------------
// Count+scan over 6656 rows from the small per-block count array.
// ---------------------------------------------------------------
__global__ void scan_k() {
    const int PER = (NROWS + 1023) / 1024;   // 7
    int tid = threadIdx.x;
    int vals[PER];
    int local = 0;
    int start = tid * PER;
    #pragma unroll
    for (int j = 0; j < PER; j++) {
        int idx = start + j;
        int v = 0;
        if (idx < NROWS) {
            int4 c = *(const int4*)(d_pcnt + idx*4);
            v = c.x + c.y + c.z + c.w;
        }
        vals[j] = v;
        local += v;
    }
    __shared__ int sh[1024];
    sh[tid] = local;
    __syncthreads();
    for (int off = 1; off < 1024; off <<= 1) {
        int v = (tid >= off) ? sh[tid - off] : 0;
        __syncthreads();
        sh[tid] += v;
        __syncthreads();
    }
    int run = sh[tid] - local;
    #pragma unroll
    for (int j = 0; j < PER; j++) {
        int idx = start + j;
        if (idx < NROWS) { d_rowcnt[idx] = run; run += vals[j]; }
    }
    if (tid == 1023) d_total = sh[1023];
}

// ---------------------------------------------------------------
// Fused fill + scatter (disjoint index ranges, order-independent).
// grid NROWS blocks of 32 threads.
// ---------------------------------------------------------------
__global__ void write_k(float* __restrict__ out) {
    int rid  = blockIdx.x;
    int lane = threadIdx.x;
    int total = d_total;
    float sig0 = d_sig[0];
    #pragma unroll
    for (int j = 0; j < 5; j++) {          // 5*NROWS = 33280 >= MAXPEAKS
        int f = rid + j * NROWS;
        if (f < MAXPEAKS && f >= total && lane < 3)
            out[3*f + lane] = (lane == 0) ? sig0 : 0.f;
    }
    int k = rid >> 9, y = rid & 511;
    int run = d_rowcnt[rid];
    float sg = d_sig[k];
    for (int w = 0; w < 16; w++) {
        unsigned word = d_maskw[rid*16 + w];
        if (word) {
            if ((word >> lane) & 1u) {
                int idx = run + __popc(word & ((1u << lane) - 1u));
                if (idx < MAXPEAKS) {
                    out[3*idx]     = sg;
                    out[3*idx + 1] = (float)y;
                    out[3*idx + 2] = (float)(w*32 + lane);
                }
            }
            run += __popc(word);
        }
    }
}

extern "C" void kernel_launch(void* const* d_in, const int* in_sizes, int n_in,
                              void* d_out, int out_size) {
    const float* x     = nullptr;
    const float* sigma = nullptr;
    for (int i = 0; i < n_in; i++) {
        if (in_sizes[i] == H * W)   x     = (const float*)d_in[i];
        else if (in_sizes[i] == NS) sigma = (const float*)d_in[i];
    }
    if (!x)     x     = (const float*)d_in[0];
    if (!sigma) sigma = (const float*)d_in[n_in - 1];

    float* out = (float*)d_out;                   // [32768, 3]

    build_kernels_k<<<NS, 128>>>(sigma);
    hblur_k<<<dim3(H, NS), 128>>>(x);
    vblur_k<<<dim3(W/VTX, H/VTY, NS), dim3(VTX, 8)>>>();
    peak_k<<<dim3(W/PTX, H/PTY, NK-2), dim3(32, 8)>>>();
    scan_k<<<1, 1024>>>();
    write_k<<<NROWS, 32>>>(out);
}

// round 16
// speedup vs baseline: 1.0288x; 1.0288x over previous
#include <cuda_runtime.h>
#include <math.h>

#define H 512
#define W 512
#define NS 14            // number of gaussian scales (K+1)
#define NK 13            // number of DoG planes (K)
#define MAXR 43
#define NROWS (NK*H)
#define THRESH 0.001f
#define MAXPEAKS 32768
#define HW (H*W)

// ---- scratch (static device memory; no allocations allowed) ----
__device__ float  d_tmpf[NS*H*W];     // after horizontal blur (fp32-rounded)
// g pyramid with 1024-float guard pads on both sides so peak_k can read
// halo cells unclamped (garbage there only consumed as neighbors of
// border-excluded pixels -> never affects results).
__device__ __align__(16) float d_gbuf[NS*H*W + 2048];
#define D_G (d_gbuf + 1024)
__device__ float  d_kx[NS*96];        // 1D kernels, fp32-rounded coeffs (padded)
__device__ int    d_rad[NS];
__device__ float  d_sig[NS];
__device__ unsigned d_maskw[NROWS*16];// 512-bit peak mask per (k,y) row
                                      // (k=0 and k=12 rows: never written, BSS zero)
__device__ int    d_pcnt[NROWS*4];    // per-(row, x-block) popcounts (k=0/12: BSS zero)
__device__ int    d_rowcnt[NROWS];    // exclusive offsets after scan
__device__ int    d_total;            // total peak count

// Anchored Fast2Sum: hi >= 2 > b >= 0 always -> error extraction exact.
#define F2S(hi_, lo_, b_) do { \
    float t2_ = __fadd_rn(hi_, b_); \
    float u_  = __fsub_rn(t2_, hi_); \
    float e_  = __fsub_rn(b_, u_); \
    hi_ = t2_; \
    lo_ = __fadd_rn(lo_, e_); \
} while (0)

// ---------------------------------------------------------------
// Build normalized 1D gaussian kernels in fp64, round to fp32.
// ---------------------------------------------------------------
__global__ void build_kernels_k(const float* __restrict__ sigma_list) {
    int i   = blockIdx.x;
    int tid = threadIdx.x;      // 128 threads
    float sf = sigma_list[i];
    double s = (double)sf;
    int r   = (int)floor(4.0 * s + 0.5);   // TRUNCATE=4
    int n   = 2 * r + 1;
    __shared__ double tmp[96];
    __shared__ double ssum;
    if (tid < n) {
        double mean = 0.5 * (double)(n - 1);
        double d = ((double)tid - mean) / (2.0 * s);
        tmp[tid] = exp(-(d * d));
    }
    __syncthreads();
    if (tid == 0) {
        double acc = 0.0;
        for (int j = 0; j < n; j++) acc += tmp[j];
        ssum = acc;
        d_rad[i] = r;
        d_sig[i] = sf;
    }
    __syncthreads();
    if (tid < 96) d_kx[i*96 + tid] = (tid < n) ? (float)(tmp[tid] / ssum) : 0.f;
}

// ---------------------------------------------------------------
// Horizontal pass. Symmetric pairing (a_l+a_r)*k, TWO pairs folded
// per anchored Fast2Sum (K=2 block compensation, validated R13/R14).
// 4 outputs/thread. blockDim 128, grid (H, NS).
// ---------------------------------------------------------------
__global__ void hblur_k(const float* __restrict__ x) {
    int y  = blockIdx.x;
    int sc = blockIdx.y;
    int r  = d_rad[sc];
    int n  = 2 * r + 1;
    __shared__ float srow[W + 2*MAXR + 8];
    __shared__ float sk[96];
    int tid = threadIdx.x;
    for (int i = tid; i < W + 2*r + 4; i += 128) {
        int xx = i - r;
        srow[i] = (xx >= 0 && xx < W) ? x[y*W + xx] : 0.f;
    }
    for (int i = tid; i < n; i += 128) sk[i] = d_kx[sc*96 + i];
    __syncthreads();

    int xo = tid * 4;
    float wl[5], wr[5];
    #pragma unroll
    for (int q = 0; q < 5; q++) {
        wl[q] = srow[xo + q];
        wr[q] = srow[xo + n - 2 + q];
    }
    float hi[4] = {2.f, 2.f, 2.f, 2.f};
    float lo[4] = {0.f, 0.f, 0.f, 0.f};

    int j = 0;
    #pragma unroll 2
    for (; j + 1 < r; j += 2) {
        float k0 = sk[j], k1 = sk[j+1];
        #pragma unroll
        for (int t = 0; t < 4; t++) {
            float s1 = __fadd_rn(wl[t],   wr[t+1]);
            float b  = __fmul_rn(s1, k0);
            float s2 = __fadd_rn(wl[t+1], wr[t]);
            b = __fmaf_rn(s2, k1, b);
            F2S(hi[t], lo[t], b);
        }
        wl[0] = wl[2]; wl[1] = wl[3]; wl[2] = wl[4];
        wl[3] = srow[xo + j + 5];
        wl[4] = srow[xo + j + 6];
        wr[4] = wr[2]; wr[3] = wr[1]; wr[2] = wr[0];
        wr[0] = srow[xo + n - 4 - j];
        wr[1] = srow[xo + n - 3 - j];
    }
    if (r & 1) {
        float kj = sk[r-1];
        float kc = sk[r];
        #pragma unroll
        for (int t = 0; t < 4; t++) {
            float s = __fadd_rn(wl[t], wr[t+1]);
            float b = __fmul_rn(s, kj);
            b = __fmaf_rn(wl[t+1], kc, b);
            F2S(hi[t], lo[t], b);
        }
    } else {
        float kc = sk[r];
        #pragma unroll
        for (int t = 0; t < 4; t++) {
            float b = __fmul_rn(wl[t], kc);
            F2S(hi[t], lo[t], b);
        }
    }
    float4 o;
    o.x = __fadd_rn(__fsub_rn(hi[0], 2.f), lo[0]);
    o.y = __fadd_rn(__fsub_rn(hi[1], 2.f), lo[1]);
    o.z = __fadd_rn(__fsub_rn(hi[2], 2.f), lo[2]);
    o.w = __fadd_rn(__fsub_rn(hi[3], 2.f), lo[3]);
    *(float4*)(d_tmpf + (size_t)(sc*H + y) * W + xo) = o;
}

// ---------------------------------------------------------------
// Vertical pass, K=2 block-compensated, DOUBLED tile (VTY=64) to
// cut halo refill: fill factor (67+2r)/64 vs (35+2r)/32.
// blockDim (32,16)=512, 4 outputs/thread, grid (16, 8, NS).
// Arithmetic bit-identical to R14's vblur.
// ---------------------------------------------------------------
#define VTX 32
#define VTY 64
__global__ void vblur_k() {
    int sc = blockIdx.z;
    int x0 = blockIdx.x * VTX;
    int y0 = blockIdx.y * VTY;
    int r  = d_rad[sc];
    int n  = 2 * r + 1;
    __shared__ float tile[(VTY + 2*MAXR + 4) * VTX];   // 154*32*4 = 19.7KB
    __shared__ float sk[96];
    int tx  = threadIdx.x;
    int tid = tx + threadIdx.y * VTX;   // 512 threads
    int rows = VTY + 2 * r + 3;
    const float* inp = d_tmpf + (size_t)sc * HW;
    for (int i = tid; i < rows * VTX; i += 512) {
        int rr = i / VTX, cc = i % VTX;
        int gy = y0 - r + rr;
        tile[i] = (gy >= 0 && gy < H) ? inp[gy*W + x0 + cc] : 0.f;
    }
    for (int i = tid; i < n; i += 512) sk[i] = d_kx[sc*96 + i];
    __syncthreads();

    int yo = threadIdx.y * 4;
    float wl[5], wr[5];
    #pragma unroll
    for (int q = 0; q < 5; q++) {
        wl[q] = tile[(yo + q)*VTX + tx];
        wr[q] = tile[(yo + n - 2 + q)*VTX + tx];
    }
    float hi[4] = {2.f, 2.f, 2.f, 2.f};
    float lo[4] = {0.f, 0.f, 0.f, 0.f};

    int j = 0;
    #pragma unroll 2
    for (; j + 1 < r; j += 2) {
        float k0 = sk[j], k1 = sk[j+1];
        #pragma unroll
        for (int t = 0; t < 4; t++) {
            float s1 = __fadd_rn(wl[t],   wr[t+1]);
            float b  = __fmul_rn(s1, k0);
            float s2 = __fadd_rn(wl[t+1], wr[t]);
            b = __fmaf_rn(s2, k1, b);
            F2S(hi[t], lo[t], b);
        }
        wl[0] = wl[2]; wl[1] = wl[3]; wl[2] = wl[4];
        wl[3] = tile[(yo + j + 5)*VTX + tx];
        wl[4] = tile[(yo + j + 6)*VTX + tx];
        wr[4] = wr[2]; wr[3] = wr[1]; wr[2] = wr[0];
        wr[0] = tile[(yo + n - 4 - j)*VTX + tx];
        wr[1] = tile[(yo + n - 3 - j)*VTX + tx];
    }
    if (r & 1) {
        float kj = sk[r-1];
        float kc = sk[r];
        #pragma unroll
        for (int t = 0; t < 4; t++) {
            float s = __fadd_rn(wl[t], wr[t+1]);
            float b = __fmul_rn(s, kj);
            b = __fmaf_rn(wl[t+1], kc, b);
            F2S(hi[t], lo[t], b);
        }
    } else {
        float kc = sk[r];
        #pragma unroll
        for (int t = 0; t < 4; t++) {
            float b = __fmul_rn(wl[t], kc);
            F2S(hi[t], lo[t], b);
        }
    }
    float* outp = D_G + (size_t)sc * HW;
    #pragma unroll
    for (int t = 0; t < 4; t++)
        outp[(y0 + yo + t)*W + x0 + tx] =
            __fadd_rn(__fsub_rn(hi[t], 2.f), lo[t]);
}

// ---------------------------------------------------------------
// FUSED DoG + peak, separable max-pool, vectorized fill (R14).
// pk = (c > THRESH) && (c >= max27) == reference semantics exactly.
// blockDim (32,8), grid (4, 64, NK-2).
// ---------------------------------------------------------------
#define PTX 128
#define PTY 8
#define TC2 136
#define NV 34
__global__ void peak_k() {
    int k  = blockIdx.z + 1;            // 1..11
    int y0 = blockIdx.y * PTY;
    int x0 = blockIdx.x * PTX;
    __shared__ __align__(16) float szmax[PTY + 2][TC2];
    __shared__ __align__(16) float sdogc[PTY + 2][TC2];
    __shared__ float svmax[PTY][TC2];
    int tx = threadIdx.x;
    int ty = threadIdx.y;
    int tid = tx + ty * 32;             // 256 threads

    float sgm1 = d_sig[k-1], sg0 = d_sig[k], sgp1 = d_sig[k+1];
    const float* gm1 = D_G + (size_t)(k-1) * HW;
    const float* g0  = gm1 + HW;
    const float* gp1 = g0  + HW;
    const float* gp2 = gp1 + HW;

    for (int idx = tid; idx < (PTY + 2) * NV; idx += 256) {
        int rr = idx / NV, cc = idx - rr * NV;
        int gi = (y0 - 1 + rr) * W + (x0 - 4) + cc * 4;
        float4 a = *(const float4*)(gm1 + gi);
        float4 b = *(const float4*)(g0  + gi);
        float4 c = *(const float4*)(gp1 + gi);
        float4 d = *(const float4*)(gp2 + gi);
        float4 dc, zm;
        {
            float m1 = (a.x - b.x) * sgm1;
            dc.x     = (b.x - c.x) * sg0;
            float p1 = (c.x - d.x) * sgp1;
            zm.x = fmaxf(fmaxf(m1, dc.x), p1);
        }
        {
            float m1 = (a.y - b.y) * sgm1;
            dc.y     = (b.y - c.y) * sg0;
            float p1 = (c.y - d.y) * sgp1;
            zm.y = fmaxf(fmaxf(m1, dc.y), p1);
        }
        {
            float m1 = (a.z - b.z) * sgm1;
            dc.z     = (b.z - c.z) * sg0;
            float p1 = (c.z - d.z) * sgp1;
            zm.z = fmaxf(fmaxf(m1, dc.z), p1);
        }
        {
            float m1 = (a.w - b.w) * sgm1;
            dc.w     = (b.w - c.w) * sg0;
            float p1 = (c.w - d.w) * sgp1;
            zm.w = fmaxf(fmaxf(m1, dc.w), p1);
        }
        *(float4*)&szmax[rr][cc*4] = zm;
        *(float4*)&sdogc[rr][cc*4] = dc;
    }
    __syncthreads();

    #pragma unroll
    for (int cc = tx; cc < TC2; cc += 32)
        svmax[ty][cc] = fmaxf(fmaxf(szmax[ty][cc], szmax[ty+1][cc]),
                              szmax[ty+2][cc]);
    __syncthreads();

    int y = y0 + ty;
    int cnt = 0;
    #pragma unroll
    for (int q = 0; q < 4; q++) {
        int x  = x0 + q * 32 + tx;
        int lx = q * 32 + tx + 4;
        bool pk = false;
        if (y >= 1 && y <= H-2 && x >= 1 && x <= W-2) {
            float c = sdogc[ty+1][lx];
            if (c > THRESH) {
                float m = fmaxf(fmaxf(svmax[ty][lx-1], svmax[ty][lx]),
                                svmax[ty][lx+1]);
                pk = (c >= m);
            }
        }
        unsigned wmask = __ballot_sync(0xFFFFFFFFu, pk);
        if (tx == 0) {
            d_maskw[(k*H + y)*16 + (x0/32 + q)] = wmask;
            cnt += __popc(wmask);
        }
    }
    if (tx == 0) d_pcnt[(k*H + y)*4 + blockIdx.x] = cnt;
}

// ---------------------------------------------------------------
// Count+scan over 6656 rows from the small per-block count array.
// ---------------------------------------------------------------
__global__ void scan_k() {
    const int PER = (NROWS + 1023) / 1024;   // 7
    int tid = threadIdx.x;
    int vals[PER];
    int local = 0;
    int start = tid * PER;
    #pragma unroll
    for (int j = 0; j < PER; j++) {
        int idx = start + j;
        int v = 0;
        if (idx < NROWS) {
            int4 c = *(const int4*)(d_pcnt + idx*4);
            v = c.x + c.y + c.z + c.w;
        }
        vals[j] = v;
        local += v;
    }
    __shared__ int sh[1024];
    sh[tid] = local;
    __syncthreads();
    for (int off = 1; off < 1024; off <<= 1) {
        int v = (tid >= off) ? sh[tid - off] : 0;
        __syncthreads();
        sh[tid] += v;
        __syncthreads();
    }
    int run = sh[tid] - local;
    #pragma unroll
    for (int j = 0; j < PER; j++) {
        int idx = start + j;
        if (idx < NROWS) { d_rowcnt[idx] = run; run += vals[j]; }
    }
    if (tid == 1023) d_total = sh[1023];
}

// ---------------------------------------------------------------
// Fused fill + scatter (disjoint index ranges, order-independent).
// grid NROWS blocks of 32 threads.
// ---------------------------------------------------------------
__global__ void write_k(float* __restrict__ out) {
    int rid  = blockIdx.x;
    int lane = threadIdx.x;
    int total = d_total;
    float sig0 = d_sig[0];
    #pragma unroll
    for (int j = 0; j < 5; j++) {          // 5*NROWS = 33280 >= MAXPEAKS
        int f = rid + j * NROWS;
        if (f < MAXPEAKS && f >= total && lane < 3)
            out[3*f + lane] = (lane == 0) ? sig0 : 0.f;
    }
    int k = rid >> 9, y = rid & 511;
    int run = d_rowcnt[rid];
    float sg = d_sig[k];
    for (int w = 0; w < 16; w++) {
        unsigned word = d_maskw[rid*16 + w];
        if (word) {
            if ((word >> lane) & 1u) {
                int idx = run + __popc(word & ((1u << lane) - 1u));
                if (idx < MAXPEAKS) {
                    out[3*idx]     = sg;
                    out[3*idx + 1] = (float)y;
                    out[3*idx + 2] = (float)(w*32 + lane);
                }
            }
            run += __popc(word);
        }
    }
}

extern "C" void kernel_launch(void* const* d_in, const int* in_sizes, int n_in,
                              void* d_out, int out_size) {
    const float* x     = nullptr;
    const float* sigma = nullptr;
    for (int i = 0; i < n_in; i++) {
        if (in_sizes[i] == H * W)   x     = (const float*)d_in[i];
        else if (in_sizes[i] == NS) sigma = (const float*)d_in[i];
    }
    if (!x)     x     = (const float*)d_in[0];
    if (!sigma) sigma = (const float*)d_in[n_in - 1];

    float* out = (float*)d_out;                   // [32768, 3]

    build_kernels_k<<<NS, 128>>>(sigma);
    hblur_k<<<dim3(H, NS), 128>>>(x);
    vblur_k<<<dim3(W/VTX, H/VTY, NS), dim3(VTX, 16)>>>();
    peak_k<<<dim3(W/PTX, H/PTY, NK-2), dim3(32, 8)>>>();
    scan_k<<<1, 1024>>>();
    write_k<<<NROWS, 32>>>(out);
}